// round 14
// baseline (speedup 1.0000x reference)
#include <cuda_runtime.h>
#include <cuda_fp16.h>
#include <math.h>
#include <stdint.h>

// ---------------- problem constants ----------------
#define C_DIM   1152
#define NHEADS  16
#define HD      72
#define B_SZ    4
#define T_SZ    16
#define S_SZ    256
#define N_TOK   4096
#define M_ROWS  16384
#define SS_STRIDE 6912
#define SCALE_ATTN 0.11785113019775792f
#define TSEC_STRIDE 18874368u   // 16384 * 1152

// ---------------- ptx helpers ----------------
__device__ __forceinline__ uint32_t smem_to_u32(const void* p) {
    uint32_t a;
    asm("{ .reg .u64 t; cvta.to.shared.u64 t, %1; cvt.u32.u64 %0, t; }" : "=r"(a) : "l"(p));
    return a;
}
__device__ __forceinline__ void cp16(uint32_t saddr, const void* gaddr) {
    asm volatile("cp.async.cg.shared.global [%0], [%1], 16;" :: "r"(saddr), "l"(gaddr));
}
__device__ __forceinline__ void cp16z(uint32_t saddr, const void* gaddr, uint32_t sz) {
    asm volatile("cp.async.cg.shared.global [%0], [%1], 16, %2;" :: "r"(saddr), "l"(gaddr), "r"(sz));
}
#define CP_COMMIT() asm volatile("cp.async.commit_group;" ::: "memory")
#define CP_WAIT(n)  asm volatile("cp.async.wait_group %0;" :: "n"(n) : "memory")

__device__ __forceinline__ void ldsm_x4(uint32_t* r, uint32_t addr) {
    asm volatile("ldmatrix.sync.aligned.m8n8.x4.shared.b16 {%0,%1,%2,%3}, [%4];"
        : "=r"(r[0]), "=r"(r[1]), "=r"(r[2]), "=r"(r[3]) : "r"(addr));
}
__device__ __forceinline__ void ldsm_x4_t(uint32_t* r, uint32_t addr) {
    asm volatile("ldmatrix.sync.aligned.m8n8.x4.trans.shared.b16 {%0,%1,%2,%3}, [%4];"
        : "=r"(r[0]), "=r"(r[1]), "=r"(r[2]), "=r"(r[3]) : "r"(addr));
}
__device__ __forceinline__ void mma16816(float* c, const uint32_t* a, uint32_t b0, uint32_t b1) {
    asm volatile("mma.sync.aligned.m16n8k16.row.col.f32.f16.f16.f32 "
        "{%0,%1,%2,%3}, {%4,%5,%6,%7}, {%8,%9}, {%0,%1,%2,%3};"
        : "+f"(c[0]), "+f"(c[1]), "+f"(c[2]), "+f"(c[3])
        : "r"(a[0]), "r"(a[1]), "r"(a[2]), "r"(a[3]), "r"(b0), "r"(b1));
}

// ---------------- scratch (device globals) ----------------
__device__ __align__(16) __half g_wt_qkv_s[3456 * 1152];
__device__ __align__(16) __half g_wt_proj_s[1152 * 1152];
__device__ __align__(16) __half g_wt_qkv_t[3456 * 1152];
__device__ __align__(16) __half g_wt_proj_t[1152 * 1152];
__device__ __align__(16) __half g_wt_q_c [1152 * 1152];
__device__ __align__(16) __half g_wt_kv_c[2304 * 1152];
__device__ __align__(16) __half g_wt_wo_c[1152 * 1152];
__device__ __align__(16) __half g_wt_fc1 [4608 * 1152];
__device__ __align__(16) __half g_wt_fc2 [1152 * 4608];
__device__ __align__(16) __half g_xm  [(size_t)M_ROWS * 1152];
__device__ __align__(16) __half g_xh  [(size_t)M_ROWS * 1152];
__device__ __align__(16) __half g_big [(size_t)M_ROWS * 4608];
__device__ __align__(16) __half g_attn[(size_t)M_ROWS * 1152];
__device__ __align__(16) __half g_kvc [512 * 2304];
__device__ __align__(16) __half g_yh  [480 * 1152];
__device__ float  g_ss  [B_SZ * SS_STRIDE];

// ---------------- fused preprocessing: 9 weight transposes + y f2h + ss ----------------
struct TWEntry { const float* w; __half* wt; int K; int N; int tile0; };
struct TWPack  {
    TWEntry e[9];
    int n_tw;
    int n_f2h;
    const float* y; __half* yh;
    const float* t; const float* table; float* ss;
};

__global__ void preproc_kernel(TWPack p)
{
    int blk = blockIdx.x;
    if (blk < p.n_tw) {
        __shared__ float tile[32][33];
        int i = 0;
        #pragma unroll
        for (int j = 1; j < 9; j++) if (blk >= p.e[j].tile0) i = j;
        const TWEntry& E = p.e[i];
        int local = blk - E.tile0;
        int ntiles_n = E.N >> 5;
        int n0 = (local % ntiles_n) << 5;
        int k0 = (local / ntiles_n) << 5;
        int tx = threadIdx.x & 31, ty = threadIdx.x >> 5;
        #pragma unroll
        for (int r = 0; r < 32; r += 8)
            tile[ty + r][tx] = E.w[(size_t)(k0 + ty + r) * E.N + n0 + tx];
        __syncthreads();
        #pragma unroll
        for (int r = 0; r < 32; r += 8)
            E.wt[(size_t)(n0 + ty + r) * E.K + k0 + tx] = __float2half(tile[tx][ty + r]);
    } else if (blk < p.n_tw + p.n_f2h) {
        int u = (blk - p.n_tw) * 256 + threadIdx.x;
        if (u < (480 * 1152) / 4) {
            float4 v = ((const float4*)p.y)[u];
            __half2 h0 = __floats2half2_rn(v.x, v.y);
            __half2 h1 = __floats2half2_rn(v.z, v.w);
            uint2 pk;
            pk.x = *(uint32_t*)&h0;
            pk.y = *(uint32_t*)&h1;
            ((uint2*)p.yh)[u] = pk;
        }
    } else {
        int u = (blk - p.n_tw - p.n_f2h) * 256 + threadIdx.x;
        if (u < B_SZ * SS_STRIDE) {
            int b = u / SS_STRIDE;
            p.ss[u] = p.table[u - b * SS_STRIDE] + p.t[u];
        }
    }
}

// ---------------- layernorm + modulate -> f16, warp-per-row (register-cached) ----------------
__global__ __launch_bounds__(256)
void ln_mod_kernel(const float* __restrict__ X, __half* __restrict__ Y,
                   const float* __restrict__ ss, int shift_idx, int scale_idx)
{
    int warp = threadIdx.x >> 5, lane = threadIdx.x & 31;
    int row = blockIdx.x * 8 + warp;
    int b = row >> 12;
    const float4* xp = (const float4*)(X + (size_t)row * C_DIM);

    float4 v[9];
    float lsum = 0.f, lsq = 0.f;
    #pragma unroll
    for (int i = 0; i < 9; i++) {
        v[i] = xp[lane + i * 32];
        lsum += v[i].x + v[i].y + v[i].z + v[i].w;
        lsq  += v[i].x * v[i].x + v[i].y * v[i].y + v[i].z * v[i].z + v[i].w * v[i].w;
    }
    #pragma unroll
    for (int off = 16; off > 0; off >>= 1) {
        lsum += __shfl_xor_sync(0xffffffffu, lsum, off);
        lsq  += __shfl_xor_sync(0xffffffffu, lsq,  off);
    }
    float mu = lsum * (1.f / (float)C_DIM);
    float var = lsq * (1.f / (float)C_DIM) - mu * mu;
    float rstd = rsqrtf(var + 1e-6f);

    const float4* sh = (const float4*)(ss + (size_t)(b * 6 + shift_idx) * C_DIM);
    const float4* sc = (const float4*)(ss + (size_t)(b * 6 + scale_idx) * C_DIM);
    uint2* yp = (uint2*)(Y + (size_t)row * C_DIM);
    #pragma unroll
    for (int i = 0; i < 9; i++) {
        float4 shv = sh[lane + i * 32];
        float4 scv = sc[lane + i * 32];
        float o0 = (v[i].x - mu) * rstd * (1.f + scv.x) + shv.x;
        float o1 = (v[i].y - mu) * rstd * (1.f + scv.y) + shv.y;
        float o2 = (v[i].z - mu) * rstd * (1.f + scv.z) + shv.z;
        float o3 = (v[i].w - mu) * rstd * (1.f + scv.w) + shv.w;
        __half2 h0 = __floats2half2_rn(o0, o1);
        __half2 h1 = __floats2half2_rn(o2, o3);
        uint2 pk;
        pk.x = *(uint32_t*)&h0;
        pk.y = *(uint32_t*)&h1;
        yp[lane + i * 32] = pk;
    }
}

// ---------------- f16 tensor-core GEMM, BK=64, 3-stage cp.async ----------------
template<int EPI>
__global__ __launch_bounds__(256, 2)
void hgemm_kernel(const __half* __restrict__ A, const __half* __restrict__ Wt,
                  const float* __restrict__ bias,
                  float* __restrict__ Out, __half* __restrict__ OutH,
                  int M, int N, int K,
                  const float* __restrict__ Res, const float* __restrict__ Gate,
                  const float* __restrict__ Cos, const float* __restrict__ Sin)
{
    extern __shared__ char gsm[];
    int tid = threadIdx.x;
    int bm = blockIdx.y * 128;
    int bn = blockIdx.x * 128;
    int warp = tid >> 5, lane = tid & 31;
    int wm = warp & 1, wn = warp >> 1;

    uint32_t aB = smem_to_u32(gsm);
    uint32_t bB = aB + 49152;

    int lrow = tid >> 1;
    int lc0 = (tid & 1) * 4;
    int agr = min(bm + lrow, M - 1);
    const __half* agp = A  + (size_t)agr * K + lc0 * 8;
    const __half* bgp = Wt + (size_t)(bn + lrow) * K + lc0 * 8;
    uint32_t sw[4];
    #pragma unroll
    for (int i = 0; i < 4; i++)
        sw[i] = (uint32_t)(lrow * 128 + (((lc0 + i) ^ (lrow & 7)) << 4));

    int numK = K >> 6;

    #pragma unroll
    for (int i = 0; i < 4; i++) { cp16(aB + sw[i], agp + i * 8); cp16(bB + sw[i], bgp + i * 8); }
    CP_COMMIT();
    #pragma unroll
    for (int i = 0; i < 4; i++) { cp16(aB + 16384 + sw[i], agp + 64 + i * 8); cp16(bB + 16384 + sw[i], bgp + 64 + i * 8); }
    CP_COMMIT();

    float acc[4][4][4];
    #pragma unroll
    for (int i = 0; i < 4; i++)
        #pragma unroll
        for (int j = 0; j < 4; j++)
            #pragma unroll
            for (int k = 0; k < 4; k++) acc[i][j][k] = 0.f;

    for (int kt = 0; kt < numK; kt++) {
        CP_WAIT(1);
        __syncthreads();
        if (kt + 2 < numK) {
            int nb = kt + 2; nb -= (nb / 3) * 3;
            int koff = (kt + 2) * 64;
            uint32_t ab2 = aB + nb * 16384, bb2 = bB + nb * 16384;
            #pragma unroll
            for (int i = 0; i < 4; i++) {
                cp16(ab2 + sw[i], agp + koff + i * 8);
                cp16(bb2 + sw[i], bgp + koff + i * 8);
            }
        }
        CP_COMMIT();

        int cb = kt; cb -= (cb / 3) * 3;
        uint32_t ab = aB + cb * 16384;
        uint32_t bb = bB + cb * 16384;
        #pragma unroll
        for (int kk = 0; kk < 4; kk++) {
            uint32_t a[4][4];
            #pragma unroll
            for (int mt = 0; mt < 4; mt++) {
                int row = wm * 64 + mt * 16 + (lane & 15);
                int c = kk * 2 + (lane >> 4);
                ldsm_x4(a[mt], ab + row * 128 + ((c ^ (row & 7)) << 4));
            }
            uint32_t b[2][4];
            #pragma unroll
            for (int p = 0; p < 2; p++) {
                int row = wn * 32 + p * 16 + ((lane >> 4) << 3) + (lane & 7);
                int c = kk * 2 + ((lane >> 3) & 1);
                ldsm_x4(b[p], bb + row * 128 + ((c ^ (row & 7)) << 4));
            }
            #pragma unroll
            for (int mt = 0; mt < 4; mt++)
                #pragma unroll
                for (int nt = 0; nt < 4; nt++)
                    mma16816(acc[mt][nt], a[mt], b[nt >> 1][(nt & 1) * 2], b[nt >> 1][(nt & 1) * 2 + 1]);
        }
    }

    if (EPI != 4) {
        bool hasH = (OutH != nullptr);
        #pragma unroll
        for (int mt = 0; mt < 4; mt++) {
            #pragma unroll
            for (int i = 0; i < 2; i++) {
                int row = bm + wm * 64 + mt * 16 + (lane >> 2) + i * 8;
                if (row >= M) continue;
                size_t orow = (size_t)row * N;
                int b6 = (row >> 12) * SS_STRIDE;
                #pragma unroll
                for (int nt = 0; nt < 4; nt++) {
                    int col = bn + wn * 32 + nt * 8 + ((lane & 3) << 1);
                    float v0 = acc[mt][nt][i * 2]     + bias[col];
                    float v1 = acc[mt][nt][i * 2 + 1] + bias[col + 1];
                    size_t o = orow + col;
                    if (EPI == 0) {
                        *(__half2*)(OutH + o) = __floats2half2_rn(v0, v1);
                    } else if (EPI == 1) {
                        v0 = Res[o]     + Gate[b6 + col]     * v0;
                        v1 = Res[o + 1] + Gate[b6 + col + 1] * v1;
                        *(float2*)(Out + o) = make_float2(v0, v1);
                        if (hasH) *(__half2*)(OutH + o) = __floats2half2_rn(v0, v1);
                    } else if (EPI == 2) {
                        v0 += Res[o]; v1 += Res[o + 1];
                        *(float2*)(Out + o) = make_float2(v0, v1);
                    } else {
                        float t0 = v0 + 0.044715f * v0 * v0 * v0;
                        float t1 = v1 + 0.044715f * v1 * v1 * v1;
                        float gg0 = 0.5f * v0 * (1.f + tanhf(0.79788456080286536f * t0));
                        float gg1 = 0.5f * v1 * (1.f + tanhf(0.79788456080286536f * t1));
                        *(__half2*)(OutH + o) = __floats2half2_rn(gg0, gg1);
                    }
                }
            }
        }
    } else {
        __syncthreads();
        __half (*ST)[136] = (__half(*)[136])gsm;
        int tconst = (bm >> 8) & 15;
        #pragma unroll
        for (int mt = 0; mt < 4; mt++) {
            #pragma unroll
            for (int i = 0; i < 2; i++) {
                int rl = wm * 64 + mt * 16 + (lane >> 2) + i * 8;
                #pragma unroll
                for (int nt = 0; nt < 4; nt++) {
                    int cl = wn * 32 + nt * 8 + ((lane & 3) << 1);
                    int col = bn + cl;
                    float v0 = acc[mt][nt][i * 2]     + bias[col];
                    float v1 = acc[mt][nt][i * 2 + 1] + bias[col + 1];
                    int sec = col / 1152;
                    if (sec < 2) {
                        int cc = col - sec * 1152;
                        int d2 = (cc % 72) >> 1;
                        float cf = __ldg(Cos + tconst * 36 + d2);
                        float sf = __ldg(Sin + tconst * 36 + d2);
                        float e = v0, od = v1;
                        v0 = e * cf - od * sf;
                        v1 = e * sf + od * cf;
                    }
                    *(__half2*)&ST[rl][cl] = __floats2half2_rn(v0, v1);
                }
            }
        }
        __syncthreads();
        int b = bm >> 12;
        int s_base = bm & 255;
        int sec = bn / 1152;
        int bnm = bn - sec * 1152;
        __half* dstsec = OutH + (size_t)sec * TSEC_STRIDE + (size_t)tconst * 72;
        #pragma unroll
        for (int it = 0; it < 32; it++) {
            int u2 = it * 256 + tid;
            int r = u2 >> 6;
            int cl = (u2 & 63) << 1;
            int cc = bnm + cl;
            int hh = cc / 72;
            int d = cc - hh * 72;
            int s = s_base + r;
            size_t dst = ((size_t)(((b << 8) | s) << 4) + hh) * 1152 + d;
            *(__half2*)(dstsec + dst) = *(__half2*)&ST[r][cl];
        }
    }
}

// ---------------- mma flash attention: 2-buffer cp.async pipeline + uniform mask branch ----
// 128-row Q tile, 8 warps x 16 rows, 2 CTA/SM.
// smem: QS[128][88] + KS[2][64][88] + VS[2][64][88] = 67584 B
#define MHA_SMEM (128*88*2 + 2*64*88*2 + 2*64*88*2)
__global__ __launch_bounds__(256, 2)
void mha_kernel(const __half* __restrict__ Q, const __half* __restrict__ K,
                const __half* __restrict__ V, __half* __restrict__ O,
                int q_ld, int kv_ld, int o_ld,
                int q_us, int kv_us, int kv_len)
{
    extern __shared__ char gsm[];
    __half (*QS)[88] = (__half(*)[88])gsm;
    uint32_t qB = smem_to_u32(gsm);
    uint32_t kB = qB + 128 * 88 * 2;           // KS[2][64][88]
    uint32_t vB = kB + 2 * 64 * 88 * 2;        // VS[2][64][88]

    int tid = threadIdx.x, warp = tid >> 5, lane = tid & 31;
    int u = blockIdx.z, h = blockIdx.y, qt = blockIdx.x;
    size_t qrow0 = (size_t)u * q_us + (size_t)qt * 128;
    size_t kvrow0 = (size_t)u * kv_us;
    int hc = h * HD;

    // zero pad cols (72..87) of all 4 KV buffers (256 rows x 2 chunks of 16B)
    for (int idx = tid; idx < 512; idx += 256) {
        int row = idx >> 1, hh = idx & 1;
        *(uint4*)(gsm + (128 * 88 + (size_t)row * 88 + 72 + hh * 8) * 2) = make_uint4(0, 0, 0, 0);
    }

    // Q tile load (plus zero-pad cols 72..79)
    {
        int r = tid >> 1, hf = tid & 1;
        const uint2* src = (const uint2*)(Q + (qrow0 + r) * q_ld + hc) + hf * 9;
        uint2* dst = (uint2*)&QS[r][0] + hf * 9;
        #pragma unroll
        for (int i = 0; i < 9; i++) dst[i] = src[i];
        if (hf) { dst[9] = make_uint2(0, 0); dst[10] = make_uint2(0, 0); }
    }

    int nchunk = (kv_len + 63) >> 6;

    auto load_chunk = [&](int jc, int bb) {
        int j0 = jc * 64;
        uint32_t kdst = kB + bb * 11264;
        uint32_t vdst = vB + bb * 11264;
        for (int idx = tid; idx < 576; idx += 256) {
            int row = idx / 9, c = idx - row * 9;
            int gj = j0 + row;
            uint32_t sz = (gj < kv_len) ? 16u : 0u;
            int gjc = (gj < kv_len) ? gj : 0;
            size_t roff = (kvrow0 + gjc) * (size_t)kv_ld + hc + c * 8;
            uint32_t soff = (uint32_t)(row * 88 + c * 8) * 2;
            cp16z(kdst + soff, K + roff, sz);
            cp16z(vdst + soff, V + roff, sz);
        }
    };

    load_chunk(0, 0);
    CP_COMMIT();

    float mrow[2] = {-1e30f, -1e30f};
    float lrow[2] = {0.f, 0.f};
    float o[9][4];
    #pragma unroll
    for (int nt = 0; nt < 9; nt++)
        #pragma unroll
        for (int j = 0; j < 4; j++) o[nt][j] = 0.f;

    for (int jc = 0; jc < nchunk; jc++) {
        int cur = jc & 1;
        CP_WAIT(0);
        __syncthreads();
        if (jc + 1 < nchunk) load_chunk(jc + 1, cur ^ 1);
        CP_COMMIT();

        uint32_t ks = kB + cur * 11264;
        uint32_t vs = vB + cur * 11264;
        int j0 = jc * 64;

        // S = Q @ K^T
        float s[8][4];
        #pragma unroll
        for (int nt = 0; nt < 8; nt++)
            #pragma unroll
            for (int j = 0; j < 4; j++) s[nt][j] = 0.f;

        #pragma unroll
        for (int kt = 0; kt < 5; kt++) {
            uint32_t a[4];
            ldsm_x4(a, qB + ((warp * 16 + (lane & 15)) * 88 + kt * 16 + (lane >> 4) * 8) * 2);
            uint32_t kb[4][4];
            #pragma unroll
            for (int p = 0; p < 4; p++)
                ldsm_x4(kb[p], ks + ((p * 16 + ((lane >> 4) << 3) + (lane & 7)) * 88
                                     + kt * 16 + ((lane >> 3) & 1) * 8) * 2);
            #pragma unroll
            for (int nt = 0; nt < 8; nt++)
                mma16816(s[nt], a, kb[nt >> 1][(nt & 1) * 2], kb[nt >> 1][(nt & 1) * 2 + 1]);
        }

        // online softmax (uniform branch: full chunks skip masking)
        bool full = (j0 + 64 <= kv_len);
        #pragma unroll
        for (int ih = 0; ih < 2; ih++) {
            float rm = -1e30f;
            if (full) {
                #pragma unroll
                for (int nt = 0; nt < 8; nt++) {
                    #pragma unroll
                    for (int jj = 0; jj < 2; jj++) {
                        float v = s[nt][ih * 2 + jj] * SCALE_ATTN;
                        s[nt][ih * 2 + jj] = v;
                        rm = fmaxf(rm, v);
                    }
                }
            } else {
                #pragma unroll
                for (int nt = 0; nt < 8; nt++) {
                    #pragma unroll
                    for (int jj = 0; jj < 2; jj++) {
                        float v = s[nt][ih * 2 + jj] * SCALE_ATTN;
                        int col = j0 + nt * 8 + (lane & 3) * 2 + jj;
                        if (col >= kv_len) v = -1e30f;
                        s[nt][ih * 2 + jj] = v;
                        rm = fmaxf(rm, v);
                    }
                }
            }
            rm = fmaxf(rm, __shfl_xor_sync(0xffffffffu, rm, 1));
            rm = fmaxf(rm, __shfl_xor_sync(0xffffffffu, rm, 2));
            float mn = fmaxf(mrow[ih], rm);
            float corr = __expf(mrow[ih] - mn);
            mrow[ih] = mn;
            float ls = 0.f;
            #pragma unroll
            for (int nt = 0; nt < 8; nt++) {
                #pragma unroll
                for (int jj = 0; jj < 2; jj++) {
                    float p = __expf(s[nt][ih * 2 + jj] - mn);
                    s[nt][ih * 2 + jj] = p;
                    ls += p;
                }
            }
            ls += __shfl_xor_sync(0xffffffffu, ls, 1);
            ls += __shfl_xor_sync(0xffffffffu, ls, 2);
            lrow[ih] = lrow[ih] * corr + ls;
            #pragma unroll
            for (int nt = 0; nt < 9; nt++) {
                o[nt][ih * 2]     *= corr;
                o[nt][ih * 2 + 1] *= corr;
            }
        }

        // O += P @ V  (V fragments via trans-ldsm from row-major VS)
        #pragma unroll
        for (int kt = 0; kt < 4; kt++) {
            uint32_t vb[5][4];
            #pragma unroll
            for (int p = 0; p < 5; p++)
                ldsm_x4_t(vb[p], vs + ((kt * 16 + ((lane >> 3) & 1) * 8 + (lane & 7)) * 88
                                        + p * 16 + (lane >> 4) * 8) * 2);
            uint32_t ap[4];
            __half2 p0 = __floats2half2_rn(s[2 * kt][0],     s[2 * kt][1]);
            __half2 p1 = __floats2half2_rn(s[2 * kt][2],     s[2 * kt][3]);
            __half2 p2 = __floats2half2_rn(s[2 * kt + 1][0], s[2 * kt + 1][1]);
            __half2 p3 = __floats2half2_rn(s[2 * kt + 1][2], s[2 * kt + 1][3]);
            ap[0] = *(uint32_t*)&p0; ap[1] = *(uint32_t*)&p1;
            ap[2] = *(uint32_t*)&p2; ap[3] = *(uint32_t*)&p3;
            #pragma unroll
            for (int nt = 0; nt < 9; nt++)
                mma16816(o[nt], ap, vb[nt >> 1][(nt & 1) * 2], vb[nt >> 1][(nt & 1) * 2 + 1]);
        }
    }

    #pragma unroll
    for (int ih = 0; ih < 2; ih++) {
        int row = warp * 16 + (lane >> 2) + ih * 8;
        float inv = 1.f / lrow[ih];
        __half* ob = O + (qrow0 + row) * (size_t)o_ld + hc;
        #pragma unroll
        for (int nt = 0; nt < 9; nt++) {
            int d = nt * 8 + (lane & 3) * 2;
            *(__half2*)(ob + d) = __floats2half2_rn(o[nt][ih * 2] * inv,
                                                    o[nt][ih * 2 + 1] * inv);
        }
    }
}

// ---------------- temporal causal attention: one warp per (b,s,h) slice ----------------
#define TMP_SMEM (8 * (16*88 + 16*88 + 80*24) * 2)
__global__ __launch_bounds__(256)
void temporal_mma_kernel(const __half* __restrict__ QKV, __half* __restrict__ O)
{
    extern __shared__ char gsm[];
    int tid = threadIdx.x, warp = tid >> 5, lane = tid & 31;
    __half* wbase = (__half*)gsm + warp * 4736;
    __half (*sQ)[88] = (__half(*)[88])wbase;
    __half (*sK)[88] = (__half(*)[88])(wbase + 1408);
    __half (*sV)[24] = (__half(*)[24])(wbase + 2816);

    int slice = blockIdx.x * 8 + warp;
    int h = slice & 15;
    int bs = slice >> 4;
    int s = bs & 255;
    int b = bs >> 8;

    const __half* qp = QKV + (size_t)slice * 1152;
    const __half* kp = qp + TSEC_STRIDE;
    const __half* vp = qp + 2u * TSEC_STRIDE;

    for (int i = lane; i < 288; i += 32) {
        int t = i / 18, d4 = (i % 18) * 4;
        *(uint2*)&sQ[t][d4] = *(const uint2*)(qp + t * 72 + d4);
        *(uint2*)&sK[t][d4] = *(const uint2*)(kp + t * 72 + d4);
    }
    if (lane < 16) {
        *(uint4*)&sQ[lane][72] = make_uint4(0, 0, 0, 0);
        *(uint4*)&sK[lane][72] = make_uint4(0, 0, 0, 0);
    }
    for (int i = lane; i < 16 * 72; i += 32) {
        int t = i / 72, d = i % 72;
        sV[d][t] = vp[i];
    }
    for (int i = lane; i < 8 * 16; i += 32)
        sV[72 + (i >> 4)][i & 15] = __float2half(0.f);
    __syncwarp();

    float sc[2][4] = {{0.f, 0.f, 0.f, 0.f}, {0.f, 0.f, 0.f, 0.f}};
    #pragma unroll
    for (int kt = 0; kt < 5; kt++) {
        uint32_t a[4], kb[4];
        ldsm_x4(a, smem_to_u32(&sQ[lane & 15][kt * 16 + (lane >> 4) * 8]));
        ldsm_x4(kb, smem_to_u32(&sK[((lane >> 4) << 3) + (lane & 7)][kt * 16 + ((lane >> 3) & 1) * 8]));
        mma16816(sc[0], a, kb[0], kb[1]);
        mma16816(sc[1], a, kb[2], kb[3]);
    }

    float inv_l[2];
    #pragma unroll
    for (int ih = 0; ih < 2; ih++) {
        int tq = (lane >> 2) + ih * 8;
        float rm = -1e30f;
        #pragma unroll
        for (int nt = 0; nt < 2; nt++)
            #pragma unroll
            for (int jj = 0; jj < 2; jj++) {
                int tk = nt * 8 + (lane & 3) * 2 + jj;
                float v = sc[nt][ih * 2 + jj] * SCALE_ATTN;
                if (tk > tq) v = -1e30f;
                sc[nt][ih * 2 + jj] = v;
                rm = fmaxf(rm, v);
            }
        rm = fmaxf(rm, __shfl_xor_sync(0xffffffffu, rm, 1));
        rm = fmaxf(rm, __shfl_xor_sync(0xffffffffu, rm, 2));
        float ls = 0.f;
        #pragma unroll
        for (int nt = 0; nt < 2; nt++)
            #pragma unroll
            for (int jj = 0; jj < 2; jj++) {
                float p = __expf(sc[nt][ih * 2 + jj] - rm);
                sc[nt][ih * 2 + jj] = p;
                ls += p;
            }
        ls += __shfl_xor_sync(0xffffffffu, ls, 1);
        ls += __shfl_xor_sync(0xffffffffu, ls, 2);
        inv_l[ih] = 1.f / ls;
    }

    uint32_t ap[4];
    __half2 p0 = __floats2half2_rn(sc[0][0], sc[0][1]);
    __half2 p1 = __floats2half2_rn(sc[0][2], sc[0][3]);
    __half2 p2 = __floats2half2_rn(sc[1][0], sc[1][1]);
    __half2 p3 = __floats2half2_rn(sc[1][2], sc[1][3]);
    ap[0] = *(uint32_t*)&p0; ap[1] = *(uint32_t*)&p1;
    ap[2] = *(uint32_t*)&p2; ap[3] = *(uint32_t*)&p3;

    float o[9][4];
    #pragma unroll
    for (int nt = 0; nt < 9; nt++)
        #pragma unroll
        for (int j = 0; j < 4; j++) o[nt][j] = 0.f;
    uint32_t vb[5][4];
    #pragma unroll
    for (int p = 0; p < 5; p++)
        ldsm_x4(vb[p], smem_to_u32(&sV[p * 16 + ((lane >> 4) << 3) + (lane & 7)][((lane >> 3) & 1) * 8]));
    #pragma unroll
    for (int nt = 0; nt < 9; nt++)
        mma16816(o[nt], ap, vb[nt >> 1][(nt & 1) * 2], vb[nt >> 1][(nt & 1) * 2 + 1]);

    #pragma unroll
    for (int ih = 0; ih < 2; ih++) {
        int tq = (lane >> 2) + ih * 8;
        size_t rowtok = (size_t)b * N_TOK + (size_t)tq * 256 + s;
        __half* ob = O + rowtok * C_DIM + h * HD;
        float inv = inv_l[ih];
        #pragma unroll
        for (int nt = 0; nt < 9; nt++) {
            int d = nt * 8 + (lane & 3) * 2;
            *(__half2*)(ob + d) = __floats2half2_rn(o[nt][ih * 2] * inv, o[nt][ih * 2 + 1] * inv);
        }
    }
}

// ---------------- host orchestration ----------------
extern "C" void kernel_launch(void* const* d_in, const int* in_sizes, int n_in,
                              void* d_out, int out_size)
{
    (void)in_sizes; (void)n_in; (void)out_size;
    const float* x_in    = (const float*)d_in[0];
    const float* y_in    = (const float*)d_in[1];
    const float* t_in    = (const float*)d_in[2];
    const float* sstab   = (const float*)d_in[3];
    const float* w_qkv_s = (const float*)d_in[4];
    const float* b_qkv_s = (const float*)d_in[5];
    const float* w_proj_s = (const float*)d_in[6];
    const float* b_proj_s = (const float*)d_in[7];
    const float* w_qkv_t = (const float*)d_in[8];
    const float* b_qkv_t = (const float*)d_in[9];
    const float* w_proj_t = (const float*)d_in[10];
    const float* b_proj_t = (const float*)d_in[11];
    const float* wq_c  = (const float*)d_in[12];
    const float* bq_c  = (const float*)d_in[13];
    const float* wkv_c = (const float*)d_in[14];
    const float* bkv_c = (const float*)d_in[15];
    const float* wo_c  = (const float*)d_in[16];
    const float* bo_c  = (const float*)d_in[17];
    const float* w_fc1 = (const float*)d_in[18];
    const float* b_fc1 = (const float*)d_in[19];
    const float* w_fc2 = (const float*)d_in[20];
    const float* b_fc2 = (const float*)d_in[21];
    const float* f_cos = (const float*)d_in[22];
    const float* f_sin = (const float*)d_in[23];
    float* out = (float*)d_out;

    float* ss;   cudaGetSymbolAddress((void**)&ss, g_ss);
    __half *wt_qkv_s, *wt_proj_s, *wt_qkv_t, *wt_proj_t, *wt_q_c, *wt_kv_c, *wt_wo_c, *wt_fc1, *wt_fc2;
    __half *xm, *xh, *big, *attn, *kvc, *yh;
    cudaGetSymbolAddress((void**)&wt_qkv_s, g_wt_qkv_s);
    cudaGetSymbolAddress((void**)&wt_proj_s, g_wt_proj_s);
    cudaGetSymbolAddress((void**)&wt_qkv_t, g_wt_qkv_t);
    cudaGetSymbolAddress((void**)&wt_proj_t, g_wt_proj_t);
    cudaGetSymbolAddress((void**)&wt_q_c,  g_wt_q_c);
    cudaGetSymbolAddress((void**)&wt_kv_c, g_wt_kv_c);
    cudaGetSymbolAddress((void**)&wt_wo_c, g_wt_wo_c);
    cudaGetSymbolAddress((void**)&wt_fc1,  g_wt_fc1);
    cudaGetSymbolAddress((void**)&wt_fc2,  g_wt_fc2);
    cudaGetSymbolAddress((void**)&xm,   g_xm);
    cudaGetSymbolAddress((void**)&xh,   g_xh);
    cudaGetSymbolAddress((void**)&big,  g_big);
    cudaGetSymbolAddress((void**)&attn, g_attn);
    cudaGetSymbolAddress((void**)&kvc,  g_kvc);
    cudaGetSymbolAddress((void**)&yh,   g_yh);

    const int GEMM_SMEM = 98304;
    cudaFuncSetAttribute(hgemm_kernel<0>, cudaFuncAttributeMaxDynamicSharedMemorySize, GEMM_SMEM);
    cudaFuncSetAttribute(hgemm_kernel<1>, cudaFuncAttributeMaxDynamicSharedMemorySize, GEMM_SMEM);
    cudaFuncSetAttribute(hgemm_kernel<2>, cudaFuncAttributeMaxDynamicSharedMemorySize, GEMM_SMEM);
    cudaFuncSetAttribute(hgemm_kernel<3>, cudaFuncAttributeMaxDynamicSharedMemorySize, GEMM_SMEM);
    cudaFuncSetAttribute(hgemm_kernel<4>, cudaFuncAttributeMaxDynamicSharedMemorySize, GEMM_SMEM);
    cudaFuncSetAttribute(mha_kernel, cudaFuncAttributeMaxDynamicSharedMemorySize, MHA_SMEM);
    cudaFuncSetAttribute(temporal_mma_kernel, cudaFuncAttributeMaxDynamicSharedMemorySize, TMP_SMEM);

    // ---- fused preprocessing ----
    TWPack pack;
    int tile_acc = 0;
    auto add = [&](int i, const float* w, __half* wt, int K, int N) {
        pack.e[i].w = w; pack.e[i].wt = wt; pack.e[i].K = K; pack.e[i].N = N;
        pack.e[i].tile0 = tile_acc;
        tile_acc += (K >> 5) * (N >> 5);
    };
    add(0, w_qkv_s,  wt_qkv_s,  1152, 3456);
    add(1, w_proj_s, wt_proj_s, 1152, 1152);
    add(2, w_qkv_t,  wt_qkv_t,  1152, 3456);
    add(3, w_proj_t, wt_proj_t, 1152, 1152);
    add(4, wq_c,     wt_q_c,    1152, 1152);
    add(5, wkv_c,    wt_kv_c,   1152, 2304);
    add(6, wo_c,     wt_wo_c,   1152, 1152);
    add(7, w_fc1,    wt_fc1,    1152, 4608);
    add(8, w_fc2,    wt_fc2,    4608, 1152);
    pack.n_tw  = tile_acc;
    pack.n_f2h = ((480 * 1152 / 4) + 255) / 256;
    pack.y = y_in; pack.yh = yh;
    pack.t = t_in; pack.table = sstab; pack.ss = ss;
    int n_ss_blocks = (B_SZ * SS_STRIDE + 255) / 256;
    preproc_kernel<<<tile_acc + pack.n_f2h + n_ss_blocks, 256>>>(pack);

    ln_mod_kernel<<<M_ROWS / 8, 256>>>(x_in, xm, ss, 0, 1);

    // spatial branch
    hgemm_kernel<0><<<dim3(27, 128), 256, GEMM_SMEM>>>(xm, wt_qkv_s, b_qkv_s,
        nullptr, big, M_ROWS, 3456, 1152, nullptr, nullptr, nullptr, nullptr);
    mha_kernel<<<dim3(2, 16, 64), 256, MHA_SMEM>>>(
        big, big + 1152, big + 2304, attn, 3456, 3456, 1152, 256, 256, 256);
    hgemm_kernel<1><<<dim3(9, 128), 256, GEMM_SMEM>>>(attn, wt_proj_s, b_proj_s,
        out, xh, M_ROWS, 1152, 1152, x_in, ss + 2 * C_DIM, nullptr, nullptr);

    // temporal branch
    hgemm_kernel<4><<<dim3(27, 128), 256, GEMM_SMEM>>>(xh, wt_qkv_t, b_qkv_t,
        nullptr, big, M_ROWS, 3456, 1152, nullptr, nullptr, f_cos, f_sin);
    temporal_mma_kernel<<<2048, 256, TMP_SMEM>>>(big, attn);
    hgemm_kernel<1><<<dim3(9, 128), 256, GEMM_SMEM>>>(attn, wt_proj_t, b_proj_t,
        out, xh, M_ROWS, 1152, 1152, out, ss + 2 * C_DIM, nullptr, nullptr);

    // cross attention
    hgemm_kernel<0><<<dim3(9, 128), 256, GEMM_SMEM>>>(xh, wt_q_c, bq_c,
        nullptr, xm, M_ROWS, 1152, 1152, nullptr, nullptr, nullptr, nullptr);
    hgemm_kernel<0><<<dim3(18, 4), 256, GEMM_SMEM>>>(yh, wt_kv_c, bkv_c,
        nullptr, kvc, 480, 2304, 1152, nullptr, nullptr, nullptr, nullptr);
    mha_kernel<<<dim3(32, 16, 4), 256, MHA_SMEM>>>(
        xm, kvc, kvc + 1152, attn, 1152, 2304, 1152, 4096, 120, 120);
    hgemm_kernel<2><<<dim3(9, 128), 256, GEMM_SMEM>>>(attn, wt_wo_c, bo_c,
        out, nullptr, M_ROWS, 1152, 1152, out, nullptr, nullptr, nullptr);

    // MLP
    ln_mod_kernel<<<M_ROWS / 8, 256>>>(out, xm, ss, 3, 4);
    hgemm_kernel<3><<<dim3(36, 128), 256, GEMM_SMEM>>>(xm, wt_fc1, b_fc1,
        nullptr, big, M_ROWS, 4608, 1152, nullptr, nullptr, nullptr, nullptr);
    hgemm_kernel<1><<<dim3(9, 128), 256, GEMM_SMEM>>>(big, wt_fc2, b_fc2,
        out, nullptr, M_ROWS, 1152, 4608, out, ss + 5 * C_DIM, nullptr, nullptr);
}

// round 15
// speedup vs baseline: 1.0042x; 1.0042x over previous
#include <cuda_runtime.h>
#include <cuda_fp16.h>
#include <math.h>
#include <stdint.h>

// ---------------- problem constants ----------------
#define C_DIM   1152
#define NHEADS  16
#define HD      72
#define B_SZ    4
#define T_SZ    16
#define S_SZ    256
#define N_TOK   4096
#define M_ROWS  16384
#define SS_STRIDE 6912
#define SCALE_ATTN 0.11785113019775792f
#define TSEC_STRIDE 18874368u   // 16384 * 1152

// ---------------- ptx helpers ----------------
__device__ __forceinline__ uint32_t smem_to_u32(const void* p) {
    uint32_t a;
    asm("{ .reg .u64 t; cvta.to.shared.u64 t, %1; cvt.u32.u64 %0, t; }" : "=r"(a) : "l"(p));
    return a;
}
__device__ __forceinline__ void cp16(uint32_t saddr, const void* gaddr) {
    asm volatile("cp.async.cg.shared.global [%0], [%1], 16;" :: "r"(saddr), "l"(gaddr));
}
__device__ __forceinline__ void cp16z(uint32_t saddr, const void* gaddr, uint32_t sz) {
    asm volatile("cp.async.cg.shared.global [%0], [%1], 16, %2;" :: "r"(saddr), "l"(gaddr), "r"(sz));
}
#define CP_COMMIT() asm volatile("cp.async.commit_group;" ::: "memory")
#define CP_WAIT(n)  asm volatile("cp.async.wait_group %0;" :: "n"(n) : "memory")

__device__ __forceinline__ void ldsm_x4(uint32_t* r, uint32_t addr) {
    asm volatile("ldmatrix.sync.aligned.m8n8.x4.shared.b16 {%0,%1,%2,%3}, [%4];"
        : "=r"(r[0]), "=r"(r[1]), "=r"(r[2]), "=r"(r[3]) : "r"(addr));
}
__device__ __forceinline__ void ldsm_x4_t(uint32_t* r, uint32_t addr) {
    asm volatile("ldmatrix.sync.aligned.m8n8.x4.trans.shared.b16 {%0,%1,%2,%3}, [%4];"
        : "=r"(r[0]), "=r"(r[1]), "=r"(r[2]), "=r"(r[3]) : "r"(addr));
}
__device__ __forceinline__ void mma16816(float* c, const uint32_t* a, uint32_t b0, uint32_t b1) {
    asm volatile("mma.sync.aligned.m16n8k16.row.col.f32.f16.f16.f32 "
        "{%0,%1,%2,%3}, {%4,%5,%6,%7}, {%8,%9}, {%0,%1,%2,%3};"
        : "+f"(c[0]), "+f"(c[1]), "+f"(c[2]), "+f"(c[3])
        : "r"(a[0]), "r"(a[1]), "r"(a[2]), "r"(a[3]), "r"(b0), "r"(b1));
}

// ---------------- scratch (device globals) ----------------
__device__ __align__(16) __half g_wt_qkv_s[3456 * 1152];
__device__ __align__(16) __half g_wt_proj_s[1152 * 1152];
__device__ __align__(16) __half g_wt_qkv_t[3456 * 1152];
__device__ __align__(16) __half g_wt_proj_t[1152 * 1152];
__device__ __align__(16) __half g_wt_q_c [1152 * 1152];
__device__ __align__(16) __half g_wt_kv_c[2304 * 1152];
__device__ __align__(16) __half g_wt_wo_c[1152 * 1152];
__device__ __align__(16) __half g_wt_fc1 [4608 * 1152];
__device__ __align__(16) __half g_wt_fc2 [1152 * 4608];
__device__ __align__(16) __half g_xm  [(size_t)M_ROWS * 1152];
__device__ __align__(16) __half g_xh  [(size_t)M_ROWS * 1152];
__device__ __align__(16) __half g_big [(size_t)M_ROWS * 4608];
__device__ __align__(16) __half g_attn[(size_t)M_ROWS * 1152];
__device__ __align__(16) __half g_kvc [512 * 2304];
__device__ __align__(16) __half g_yh  [480 * 1152];
__device__ float  g_ss  [B_SZ * SS_STRIDE];

// ---------------- fused preprocessing: 9 weight transposes + y f2h + ss ----------------
struct TWEntry { const float* w; __half* wt; int K; int N; int tile0; };
struct TWPack  {
    TWEntry e[9];
    int n_tw;
    int n_f2h;
    const float* y; __half* yh;
    const float* t; const float* table; float* ss;
};

__global__ void preproc_kernel(TWPack p)
{
    int blk = blockIdx.x;
    if (blk < p.n_tw) {
        __shared__ float tile[32][33];
        int i = 0;
        #pragma unroll
        for (int j = 1; j < 9; j++) if (blk >= p.e[j].tile0) i = j;
        const TWEntry& E = p.e[i];
        int local = blk - E.tile0;
        int ntiles_n = E.N >> 5;
        int n0 = (local % ntiles_n) << 5;
        int k0 = (local / ntiles_n) << 5;
        int tx = threadIdx.x & 31, ty = threadIdx.x >> 5;
        #pragma unroll
        for (int r = 0; r < 32; r += 8)
            tile[ty + r][tx] = E.w[(size_t)(k0 + ty + r) * E.N + n0 + tx];
        __syncthreads();
        #pragma unroll
        for (int r = 0; r < 32; r += 8)
            E.wt[(size_t)(n0 + ty + r) * E.K + k0 + tx] = __float2half(tile[tx][ty + r]);
    } else if (blk < p.n_tw + p.n_f2h) {
        int u = (blk - p.n_tw) * 256 + threadIdx.x;
        if (u < (480 * 1152) / 4) {
            float4 v = ((const float4*)p.y)[u];
            __half2 h0 = __floats2half2_rn(v.x, v.y);
            __half2 h1 = __floats2half2_rn(v.z, v.w);
            uint2 pk;
            pk.x = *(uint32_t*)&h0;
            pk.y = *(uint32_t*)&h1;
            ((uint2*)p.yh)[u] = pk;
        }
    } else {
        int u = (blk - p.n_tw - p.n_f2h) * 256 + threadIdx.x;
        if (u < B_SZ * SS_STRIDE) {
            int b = u / SS_STRIDE;
            p.ss[u] = p.table[u - b * SS_STRIDE] + p.t[u];
        }
    }
}

// ---------------- layernorm + modulate -> f16, warp-per-row (register-cached) ----------------
__global__ __launch_bounds__(256)
void ln_mod_kernel(const float* __restrict__ X, __half* __restrict__ Y,
                   const float* __restrict__ ss, int shift_idx, int scale_idx)
{
    int warp = threadIdx.x >> 5, lane = threadIdx.x & 31;
    int row = blockIdx.x * 8 + warp;
    int b = row >> 12;
    const float4* xp = (const float4*)(X + (size_t)row * C_DIM);

    float4 v[9];
    float lsum = 0.f, lsq = 0.f;
    #pragma unroll
    for (int i = 0; i < 9; i++) {
        v[i] = xp[lane + i * 32];
        lsum += v[i].x + v[i].y + v[i].z + v[i].w;
        lsq  += v[i].x * v[i].x + v[i].y * v[i].y + v[i].z * v[i].z + v[i].w * v[i].w;
    }
    #pragma unroll
    for (int off = 16; off > 0; off >>= 1) {
        lsum += __shfl_xor_sync(0xffffffffu, lsum, off);
        lsq  += __shfl_xor_sync(0xffffffffu, lsq,  off);
    }
    float mu = lsum * (1.f / (float)C_DIM);
    float var = lsq * (1.f / (float)C_DIM) - mu * mu;
    float rstd = rsqrtf(var + 1e-6f);

    const float4* sh = (const float4*)(ss + (size_t)(b * 6 + shift_idx) * C_DIM);
    const float4* sc = (const float4*)(ss + (size_t)(b * 6 + scale_idx) * C_DIM);
    uint2* yp = (uint2*)(Y + (size_t)row * C_DIM);
    #pragma unroll
    for (int i = 0; i < 9; i++) {
        float4 shv = sh[lane + i * 32];
        float4 scv = sc[lane + i * 32];
        float o0 = (v[i].x - mu) * rstd * (1.f + scv.x) + shv.x;
        float o1 = (v[i].y - mu) * rstd * (1.f + scv.y) + shv.y;
        float o2 = (v[i].z - mu) * rstd * (1.f + scv.z) + shv.z;
        float o3 = (v[i].w - mu) * rstd * (1.f + scv.w) + shv.w;
        __half2 h0 = __floats2half2_rn(o0, o1);
        __half2 h1 = __floats2half2_rn(o2, o3);
        uint2 pk;
        pk.x = *(uint32_t*)&h0;
        pk.y = *(uint32_t*)&h1;
        yp[lane + i * 32] = pk;
    }
}

// ---------------- f16 tensor-core GEMM, BK=64, 3-stage cp.async ----------------
template<int EPI>
__global__ __launch_bounds__(256, 2)
void hgemm_kernel(const __half* __restrict__ A, const __half* __restrict__ Wt,
                  const float* __restrict__ bias,
                  float* __restrict__ Out, __half* __restrict__ OutH,
                  int M, int N, int K,
                  const float* __restrict__ Res, const float* __restrict__ Gate,
                  const float* __restrict__ Cos, const float* __restrict__ Sin)
{
    extern __shared__ char gsm[];
    int tid = threadIdx.x;
    int bm = blockIdx.y * 128;
    int bn = blockIdx.x * 128;
    int warp = tid >> 5, lane = tid & 31;
    int wm = warp & 1, wn = warp >> 1;

    uint32_t aB = smem_to_u32(gsm);
    uint32_t bB = aB + 49152;

    int lrow = tid >> 1;
    int lc0 = (tid & 1) * 4;
    int agr = min(bm + lrow, M - 1);
    const __half* agp = A  + (size_t)agr * K + lc0 * 8;
    const __half* bgp = Wt + (size_t)(bn + lrow) * K + lc0 * 8;
    uint32_t sw[4];
    #pragma unroll
    for (int i = 0; i < 4; i++)
        sw[i] = (uint32_t)(lrow * 128 + (((lc0 + i) ^ (lrow & 7)) << 4));

    int numK = K >> 6;

    #pragma unroll
    for (int i = 0; i < 4; i++) { cp16(aB + sw[i], agp + i * 8); cp16(bB + sw[i], bgp + i * 8); }
    CP_COMMIT();
    #pragma unroll
    for (int i = 0; i < 4; i++) { cp16(aB + 16384 + sw[i], agp + 64 + i * 8); cp16(bB + 16384 + sw[i], bgp + 64 + i * 8); }
    CP_COMMIT();

    float acc[4][4][4];
    #pragma unroll
    for (int i = 0; i < 4; i++)
        #pragma unroll
        for (int j = 0; j < 4; j++)
            #pragma unroll
            for (int k = 0; k < 4; k++) acc[i][j][k] = 0.f;

    for (int kt = 0; kt < numK; kt++) {
        CP_WAIT(1);
        __syncthreads();
        if (kt + 2 < numK) {
            int nb = kt + 2; nb -= (nb / 3) * 3;
            int koff = (kt + 2) * 64;
            uint32_t ab2 = aB + nb * 16384, bb2 = bB + nb * 16384;
            #pragma unroll
            for (int i = 0; i < 4; i++) {
                cp16(ab2 + sw[i], agp + koff + i * 8);
                cp16(bb2 + sw[i], bgp + koff + i * 8);
            }
        }
        CP_COMMIT();

        int cb = kt; cb -= (cb / 3) * 3;
        uint32_t ab = aB + cb * 16384;
        uint32_t bb = bB + cb * 16384;
        #pragma unroll
        for (int kk = 0; kk < 4; kk++) {
            uint32_t a[4][4];
            #pragma unroll
            for (int mt = 0; mt < 4; mt++) {
                int row = wm * 64 + mt * 16 + (lane & 15);
                int c = kk * 2 + (lane >> 4);
                ldsm_x4(a[mt], ab + row * 128 + ((c ^ (row & 7)) << 4));
            }
            uint32_t b[2][4];
            #pragma unroll
            for (int p = 0; p < 2; p++) {
                int row = wn * 32 + p * 16 + ((lane >> 4) << 3) + (lane & 7);
                int c = kk * 2 + ((lane >> 3) & 1);
                ldsm_x4(b[p], bb + row * 128 + ((c ^ (row & 7)) << 4));
            }
            #pragma unroll
            for (int mt = 0; mt < 4; mt++)
                #pragma unroll
                for (int nt = 0; nt < 4; nt++)
                    mma16816(acc[mt][nt], a[mt], b[nt >> 1][(nt & 1) * 2], b[nt >> 1][(nt & 1) * 2 + 1]);
        }
    }

    if (EPI != 4) {
        bool hasH = (OutH != nullptr);
        #pragma unroll
        for (int mt = 0; mt < 4; mt++) {
            #pragma unroll
            for (int i = 0; i < 2; i++) {
                int row = bm + wm * 64 + mt * 16 + (lane >> 2) + i * 8;
                if (row >= M) continue;
                size_t orow = (size_t)row * N;
                int b6 = (row >> 12) * SS_STRIDE;
                #pragma unroll
                for (int nt = 0; nt < 4; nt++) {
                    int col = bn + wn * 32 + nt * 8 + ((lane & 3) << 1);
                    float v0 = acc[mt][nt][i * 2]     + bias[col];
                    float v1 = acc[mt][nt][i * 2 + 1] + bias[col + 1];
                    size_t o = orow + col;
                    if (EPI == 0) {
                        *(__half2*)(OutH + o) = __floats2half2_rn(v0, v1);
                    } else if (EPI == 1) {
                        v0 = Res[o]     + Gate[b6 + col]     * v0;
                        v1 = Res[o + 1] + Gate[b6 + col + 1] * v1;
                        *(float2*)(Out + o) = make_float2(v0, v1);
                        if (hasH) *(__half2*)(OutH + o) = __floats2half2_rn(v0, v1);
                    } else if (EPI == 2) {
                        v0 += Res[o]; v1 += Res[o + 1];
                        *(float2*)(Out + o) = make_float2(v0, v1);
                    } else {
                        float t0 = v0 + 0.044715f * v0 * v0 * v0;
                        float t1 = v1 + 0.044715f * v1 * v1 * v1;
                        float gg0 = 0.5f * v0 * (1.f + tanhf(0.79788456080286536f * t0));
                        float gg1 = 0.5f * v1 * (1.f + tanhf(0.79788456080286536f * t1));
                        *(__half2*)(OutH + o) = __floats2half2_rn(gg0, gg1);
                    }
                }
            }
        }
    } else {
        __syncthreads();
        __half (*ST)[136] = (__half(*)[136])gsm;
        int tconst = (bm >> 8) & 15;
        #pragma unroll
        for (int mt = 0; mt < 4; mt++) {
            #pragma unroll
            for (int i = 0; i < 2; i++) {
                int rl = wm * 64 + mt * 16 + (lane >> 2) + i * 8;
                #pragma unroll
                for (int nt = 0; nt < 4; nt++) {
                    int cl = wn * 32 + nt * 8 + ((lane & 3) << 1);
                    int col = bn + cl;
                    float v0 = acc[mt][nt][i * 2]     + bias[col];
                    float v1 = acc[mt][nt][i * 2 + 1] + bias[col + 1];
                    int sec = col / 1152;
                    if (sec < 2) {
                        int cc = col - sec * 1152;
                        int d2 = (cc % 72) >> 1;
                        float cf = __ldg(Cos + tconst * 36 + d2);
                        float sf = __ldg(Sin + tconst * 36 + d2);
                        float e = v0, od = v1;
                        v0 = e * cf - od * sf;
                        v1 = e * sf + od * cf;
                    }
                    *(__half2*)&ST[rl][cl] = __floats2half2_rn(v0, v1);
                }
            }
        }
        __syncthreads();
        int b = bm >> 12;
        int s_base = bm & 255;
        int sec = bn / 1152;
        int bnm = bn - sec * 1152;
        __half* dstsec = OutH + (size_t)sec * TSEC_STRIDE + (size_t)tconst * 72;
        #pragma unroll
        for (int it = 0; it < 32; it++) {
            int u2 = it * 256 + tid;
            int r = u2 >> 6;
            int cl = (u2 & 63) << 1;
            int cc = bnm + cl;
            int hh = cc / 72;
            int d = cc - hh * 72;
            int s = s_base + r;
            size_t dst = ((size_t)(((b << 8) | s) << 4) + hh) * 1152 + d;
            *(__half2*)(dstsec + dst) = *(__half2*)&ST[r][cl];
        }
    }
}

// ---------------- dual GEMM (EPI 0): q_c tiles (y<128) + kvc tiles (y>=128) in one launch ----
__global__ __launch_bounds__(256, 2)
void hgemm_dual_kernel(const __half* __restrict__ A1, const __half* __restrict__ W1,
                       const float* __restrict__ b1, __half* __restrict__ O1,
                       const __half* __restrict__ A2, const __half* __restrict__ W2,
                       const float* __restrict__ b2, __half* __restrict__ O2)
{
    extern __shared__ char gsm[];
    int tid = threadIdx.x;

    const __half* A; const __half* Wt; const float* bias; __half* OutH;
    int M, N, bm, bn;
    if (blockIdx.y < 128) {
        if (blockIdx.x >= 9) return;
        A = A1; Wt = W1; bias = b1; OutH = O1; M = M_ROWS; N = 1152;
        bm = blockIdx.y * 128; bn = blockIdx.x * 128;
    } else {
        A = A2; Wt = W2; bias = b2; OutH = O2; M = 480; N = 2304;
        bm = (blockIdx.y - 128) * 128; bn = blockIdx.x * 128;
    }
    const int K = 1152;

    int warp = tid >> 5, lane = tid & 31;
    int wm = warp & 1, wn = warp >> 1;

    uint32_t aB = smem_to_u32(gsm);
    uint32_t bB = aB + 49152;

    int lrow = tid >> 1;
    int lc0 = (tid & 1) * 4;
    int agr = min(bm + lrow, M - 1);
    const __half* agp = A  + (size_t)agr * K + lc0 * 8;
    const __half* bgp = Wt + (size_t)(bn + lrow) * K + lc0 * 8;
    uint32_t sw[4];
    #pragma unroll
    for (int i = 0; i < 4; i++)
        sw[i] = (uint32_t)(lrow * 128 + (((lc0 + i) ^ (lrow & 7)) << 4));

    const int numK = K >> 6;

    #pragma unroll
    for (int i = 0; i < 4; i++) { cp16(aB + sw[i], agp + i * 8); cp16(bB + sw[i], bgp + i * 8); }
    CP_COMMIT();
    #pragma unroll
    for (int i = 0; i < 4; i++) { cp16(aB + 16384 + sw[i], agp + 64 + i * 8); cp16(bB + 16384 + sw[i], bgp + 64 + i * 8); }
    CP_COMMIT();

    float acc[4][4][4];
    #pragma unroll
    for (int i = 0; i < 4; i++)
        #pragma unroll
        for (int j = 0; j < 4; j++)
            #pragma unroll
            for (int k = 0; k < 4; k++) acc[i][j][k] = 0.f;

    for (int kt = 0; kt < numK; kt++) {
        CP_WAIT(1);
        __syncthreads();
        if (kt + 2 < numK) {
            int nb = kt + 2; nb -= (nb / 3) * 3;
            int koff = (kt + 2) * 64;
            uint32_t ab2 = aB + nb * 16384, bb2 = bB + nb * 16384;
            #pragma unroll
            for (int i = 0; i < 4; i++) {
                cp16(ab2 + sw[i], agp + koff + i * 8);
                cp16(bb2 + sw[i], bgp + koff + i * 8);
            }
        }
        CP_COMMIT();

        int cb = kt; cb -= (cb / 3) * 3;
        uint32_t ab = aB + cb * 16384;
        uint32_t bb = bB + cb * 16384;
        #pragma unroll
        for (int kk = 0; kk < 4; kk++) {
            uint32_t a[4][4];
            #pragma unroll
            for (int mt = 0; mt < 4; mt++) {
                int row = wm * 64 + mt * 16 + (lane & 15);
                int c = kk * 2 + (lane >> 4);
                ldsm_x4(a[mt], ab + row * 128 + ((c ^ (row & 7)) << 4));
            }
            uint32_t b[2][4];
            #pragma unroll
            for (int p = 0; p < 2; p++) {
                int row = wn * 32 + p * 16 + ((lane >> 4) << 3) + (lane & 7);
                int c = kk * 2 + ((lane >> 3) & 1);
                ldsm_x4(b[p], bb + row * 128 + ((c ^ (row & 7)) << 4));
            }
            #pragma unroll
            for (int mt = 0; mt < 4; mt++)
                #pragma unroll
                for (int nt = 0; nt < 4; nt++)
                    mma16816(acc[mt][nt], a[mt], b[nt >> 1][(nt & 1) * 2], b[nt >> 1][(nt & 1) * 2 + 1]);
        }
    }

    #pragma unroll
    for (int mt = 0; mt < 4; mt++) {
        #pragma unroll
        for (int i = 0; i < 2; i++) {
            int row = bm + wm * 64 + mt * 16 + (lane >> 2) + i * 8;
            if (row >= M) continue;
            size_t orow = (size_t)row * N;
            #pragma unroll
            for (int nt = 0; nt < 4; nt++) {
                int col = bn + wn * 32 + nt * 8 + ((lane & 3) << 1);
                float v0 = acc[mt][nt][i * 2]     + bias[col];
                float v1 = acc[mt][nt][i * 2 + 1] + bias[col + 1];
                *(__half2*)(OutH + orow + col) = __floats2half2_rn(v0, v1);
            }
        }
    }
}

// ---------------- mma flash attention: 2-buffer cp.async pipeline (round-12 exact) ----------
// 128-row Q tile, 8 warps x 16 rows, 2 CTA/SM.
// smem: QS[128][88] + KS[2][64][88] + VS[2][64][88] = 67584 B
#define MHA_SMEM (128*88*2 + 2*64*88*2 + 2*64*88*2)
__global__ __launch_bounds__(256, 2)
void mha_kernel(const __half* __restrict__ Q, const __half* __restrict__ K,
                const __half* __restrict__ V, __half* __restrict__ O,
                int q_ld, int kv_ld, int o_ld,
                int q_us, int kv_us, int kv_len)
{
    extern __shared__ char gsm[];
    __half (*QS)[88] = (__half(*)[88])gsm;
    uint32_t qB = smem_to_u32(gsm);
    uint32_t kB = qB + 128 * 88 * 2;           // KS[2][64][88]
    uint32_t vB = kB + 2 * 64 * 88 * 2;        // VS[2][64][88]

    int tid = threadIdx.x, warp = tid >> 5, lane = tid & 31;
    int u = blockIdx.z, h = blockIdx.y, qt = blockIdx.x;
    size_t qrow0 = (size_t)u * q_us + (size_t)qt * 128;
    size_t kvrow0 = (size_t)u * kv_us;
    int hc = h * HD;

    // zero pad cols (72..87) of all 4 KV buffers
    for (int idx = tid; idx < 512; idx += 256) {
        int row = idx >> 1, hh = idx & 1;
        *(uint4*)(gsm + (128 * 88 + (size_t)row * 88 + 72 + hh * 8) * 2) = make_uint4(0, 0, 0, 0);
    }

    // Q tile load (plus zero-pad cols 72..79)
    {
        int r = tid >> 1, hf = tid & 1;
        const uint2* src = (const uint2*)(Q + (qrow0 + r) * q_ld + hc) + hf * 9;
        uint2* dst = (uint2*)&QS[r][0] + hf * 9;
        #pragma unroll
        for (int i = 0; i < 9; i++) dst[i] = src[i];
        if (hf) { dst[9] = make_uint2(0, 0); dst[10] = make_uint2(0, 0); }
    }

    int nchunk = (kv_len + 63) >> 6;

    auto load_chunk = [&](int jc, int bb) {
        int j0 = jc * 64;
        uint32_t kdst = kB + bb * 11264;
        uint32_t vdst = vB + bb * 11264;
        for (int idx = tid; idx < 576; idx += 256) {
            int row = idx / 9, c = idx - row * 9;
            int gj = j0 + row;
            uint32_t sz = (gj < kv_len) ? 16u : 0u;
            int gjc = (gj < kv_len) ? gj : 0;
            size_t roff = (kvrow0 + gjc) * (size_t)kv_ld + hc + c * 8;
            uint32_t soff = (uint32_t)(row * 88 + c * 8) * 2;
            cp16z(kdst + soff, K + roff, sz);
            cp16z(vdst + soff, V + roff, sz);
        }
    };

    load_chunk(0, 0);
    CP_COMMIT();

    float mrow[2] = {-1e30f, -1e30f};
    float lrow[2] = {0.f, 0.f};
    float o[9][4];
    #pragma unroll
    for (int nt = 0; nt < 9; nt++)
        #pragma unroll
        for (int j = 0; j < 4; j++) o[nt][j] = 0.f;

    for (int jc = 0; jc < nchunk; jc++) {
        int cur = jc & 1;
        CP_WAIT(0);
        __syncthreads();
        if (jc + 1 < nchunk) load_chunk(jc + 1, cur ^ 1);
        CP_COMMIT();

        uint32_t ks = kB + cur * 11264;
        uint32_t vs = vB + cur * 11264;
        int j0 = jc * 64;

        // S = Q @ K^T
        float s[8][4];
        #pragma unroll
        for (int nt = 0; nt < 8; nt++)
            #pragma unroll
            for (int j = 0; j < 4; j++) s[nt][j] = 0.f;

        #pragma unroll
        for (int kt = 0; kt < 5; kt++) {
            uint32_t a[4];
            ldsm_x4(a, qB + ((warp * 16 + (lane & 15)) * 88 + kt * 16 + (lane >> 4) * 8) * 2);
            uint32_t kb[4][4];
            #pragma unroll
            for (int p = 0; p < 4; p++)
                ldsm_x4(kb[p], ks + ((p * 16 + ((lane >> 4) << 3) + (lane & 7)) * 88
                                     + kt * 16 + ((lane >> 3) & 1) * 8) * 2);
            #pragma unroll
            for (int nt = 0; nt < 8; nt++)
                mma16816(s[nt], a, kb[nt >> 1][(nt & 1) * 2], kb[nt >> 1][(nt & 1) * 2 + 1]);
        }

        // online softmax
        #pragma unroll
        for (int ih = 0; ih < 2; ih++) {
            float rm = -1e30f;
            #pragma unroll
            for (int nt = 0; nt < 8; nt++) {
                #pragma unroll
                for (int jj = 0; jj < 2; jj++) {
                    float v = s[nt][ih * 2 + jj] * SCALE_ATTN;
                    int col = j0 + nt * 8 + (lane & 3) * 2 + jj;
                    if (col >= kv_len) v = -1e30f;
                    s[nt][ih * 2 + jj] = v;
                    rm = fmaxf(rm, v);
                }
            }
            rm = fmaxf(rm, __shfl_xor_sync(0xffffffffu, rm, 1));
            rm = fmaxf(rm, __shfl_xor_sync(0xffffffffu, rm, 2));
            float mn = fmaxf(mrow[ih], rm);
            float corr = __expf(mrow[ih] - mn);
            mrow[ih] = mn;
            float ls = 0.f;
            #pragma unroll
            for (int nt = 0; nt < 8; nt++) {
                #pragma unroll
                for (int jj = 0; jj < 2; jj++) {
                    float p = __expf(s[nt][ih * 2 + jj] - mn);
                    s[nt][ih * 2 + jj] = p;
                    ls += p;
                }
            }
            ls += __shfl_xor_sync(0xffffffffu, ls, 1);
            ls += __shfl_xor_sync(0xffffffffu, ls, 2);
            lrow[ih] = lrow[ih] * corr + ls;
            #pragma unroll
            for (int nt = 0; nt < 9; nt++) {
                o[nt][ih * 2]     *= corr;
                o[nt][ih * 2 + 1] *= corr;
            }
        }

        // O += P @ V  (V fragments via trans-ldsm from row-major VS)
        #pragma unroll
        for (int kt = 0; kt < 4; kt++) {
            uint32_t vb[5][4];
            #pragma unroll
            for (int p = 0; p < 5; p++)
                ldsm_x4_t(vb[p], vs + ((kt * 16 + ((lane >> 3) & 1) * 8 + (lane & 7)) * 88
                                        + p * 16 + (lane >> 4) * 8) * 2);
            uint32_t ap[4];
            __half2 p0 = __floats2half2_rn(s[2 * kt][0],     s[2 * kt][1]);
            __half2 p1 = __floats2half2_rn(s[2 * kt][2],     s[2 * kt][3]);
            __half2 p2 = __floats2half2_rn(s[2 * kt + 1][0], s[2 * kt + 1][1]);
            __half2 p3 = __floats2half2_rn(s[2 * kt + 1][2], s[2 * kt + 1][3]);
            ap[0] = *(uint32_t*)&p0; ap[1] = *(uint32_t*)&p1;
            ap[2] = *(uint32_t*)&p2; ap[3] = *(uint32_t*)&p3;
            #pragma unroll
            for (int nt = 0; nt < 9; nt++)
                mma16816(o[nt], ap, vb[nt >> 1][(nt & 1) * 2], vb[nt >> 1][(nt & 1) * 2 + 1]);
        }
    }

    #pragma unroll
    for (int ih = 0; ih < 2; ih++) {
        int row = warp * 16 + (lane >> 2) + ih * 8;
        float inv = 1.f / lrow[ih];
        __half* ob = O + (qrow0 + row) * (size_t)o_ld + hc;
        #pragma unroll
        for (int nt = 0; nt < 9; nt++) {
            int d = nt * 8 + (lane & 3) * 2;
            *(__half2*)(ob + d) = __floats2half2_rn(o[nt][ih * 2] * inv,
                                                    o[nt][ih * 2 + 1] * inv);
        }
    }
}

// ---------------- temporal causal attention: one warp per (b,s,h) slice ----------------
#define TMP_SMEM (8 * (16*88 + 16*88 + 80*24) * 2)
__global__ __launch_bounds__(256)
void temporal_mma_kernel(const __half* __restrict__ QKV, __half* __restrict__ O)
{
    extern __shared__ char gsm[];
    int tid = threadIdx.x, warp = tid >> 5, lane = tid & 31;
    __half* wbase = (__half*)gsm + warp * 4736;
    __half (*sQ)[88] = (__half(*)[88])wbase;
    __half (*sK)[88] = (__half(*)[88])(wbase + 1408);
    __half (*sV)[24] = (__half(*)[24])(wbase + 2816);

    int slice = blockIdx.x * 8 + warp;
    int h = slice & 15;
    int bs = slice >> 4;
    int s = bs & 255;
    int b = bs >> 8;

    const __half* qp = QKV + (size_t)slice * 1152;
    const __half* kp = qp + TSEC_STRIDE;
    const __half* vp = qp + 2u * TSEC_STRIDE;

    for (int i = lane; i < 288; i += 32) {
        int t = i / 18, d4 = (i % 18) * 4;
        *(uint2*)&sQ[t][d4] = *(const uint2*)(qp + t * 72 + d4);
        *(uint2*)&sK[t][d4] = *(const uint2*)(kp + t * 72 + d4);
    }
    if (lane < 16) {
        *(uint4*)&sQ[lane][72] = make_uint4(0, 0, 0, 0);
        *(uint4*)&sK[lane][72] = make_uint4(0, 0, 0, 0);
    }
    for (int i = lane; i < 16 * 72; i += 32) {
        int t = i / 72, d = i % 72;
        sV[d][t] = vp[i];
    }
    for (int i = lane; i < 8 * 16; i += 32)
        sV[72 + (i >> 4)][i & 15] = __float2half(0.f);
    __syncwarp();

    float sc[2][4] = {{0.f, 0.f, 0.f, 0.f}, {0.f, 0.f, 0.f, 0.f}};
    #pragma unroll
    for (int kt = 0; kt < 5; kt++) {
        uint32_t a[4], kb[4];
        ldsm_x4(a, smem_to_u32(&sQ[lane & 15][kt * 16 + (lane >> 4) * 8]));
        ldsm_x4(kb, smem_to_u32(&sK[((lane >> 4) << 3) + (lane & 7)][kt * 16 + ((lane >> 3) & 1) * 8]));
        mma16816(sc[0], a, kb[0], kb[1]);
        mma16816(sc[1], a, kb[2], kb[3]);
    }

    float inv_l[2];
    #pragma unroll
    for (int ih = 0; ih < 2; ih++) {
        int tq = (lane >> 2) + ih * 8;
        float rm = -1e30f;
        #pragma unroll
        for (int nt = 0; nt < 2; nt++)
            #pragma unroll
            for (int jj = 0; jj < 2; jj++) {
                int tk = nt * 8 + (lane & 3) * 2 + jj;
                float v = sc[nt][ih * 2 + jj] * SCALE_ATTN;
                if (tk > tq) v = -1e30f;
                sc[nt][ih * 2 + jj] = v;
                rm = fmaxf(rm, v);
            }
        rm = fmaxf(rm, __shfl_xor_sync(0xffffffffu, rm, 1));
        rm = fmaxf(rm, __shfl_xor_sync(0xffffffffu, rm, 2));
        float ls = 0.f;
        #pragma unroll
        for (int nt = 0; nt < 2; nt++)
            #pragma unroll
            for (int jj = 0; jj < 2; jj++) {
                float p = __expf(sc[nt][ih * 2 + jj] - rm);
                sc[nt][ih * 2 + jj] = p;
                ls += p;
            }
        ls += __shfl_xor_sync(0xffffffffu, ls, 1);
        ls += __shfl_xor_sync(0xffffffffu, ls, 2);
        inv_l[ih] = 1.f / ls;
    }

    uint32_t ap[4];
    __half2 p0 = __floats2half2_rn(sc[0][0], sc[0][1]);
    __half2 p1 = __floats2half2_rn(sc[0][2], sc[0][3]);
    __half2 p2 = __floats2half2_rn(sc[1][0], sc[1][1]);
    __half2 p3 = __floats2half2_rn(sc[1][2], sc[1][3]);
    ap[0] = *(uint32_t*)&p0; ap[1] = *(uint32_t*)&p1;
    ap[2] = *(uint32_t*)&p2; ap[3] = *(uint32_t*)&p3;

    float o[9][4];
    #pragma unroll
    for (int nt = 0; nt < 9; nt++)
        #pragma unroll
        for (int j = 0; j < 4; j++) o[nt][j] = 0.f;
    uint32_t vb[5][4];
    #pragma unroll
    for (int p = 0; p < 5; p++)
        ldsm_x4(vb[p], smem_to_u32(&sV[p * 16 + ((lane >> 4) << 3) + (lane & 7)][((lane >> 3) & 1) * 8]));
    #pragma unroll
    for (int nt = 0; nt < 9; nt++)
        mma16816(o[nt], ap, vb[nt >> 1][(nt & 1) * 2], vb[nt >> 1][(nt & 1) * 2 + 1]);

    #pragma unroll
    for (int ih = 0; ih < 2; ih++) {
        int tq = (lane >> 2) + ih * 8;
        size_t rowtok = (size_t)b * N_TOK + (size_t)tq * 256 + s;
        __half* ob = O + rowtok * C_DIM + h * HD;
        float inv = inv_l[ih];
        #pragma unroll
        for (int nt = 0; nt < 9; nt++) {
            int d = nt * 8 + (lane & 3) * 2;
            *(__half2*)(ob + d) = __floats2half2_rn(o[nt][ih * 2] * inv, o[nt][ih * 2 + 1] * inv);
        }
    }
}

// ---------------- host orchestration ----------------
extern "C" void kernel_launch(void* const* d_in, const int* in_sizes, int n_in,
                              void* d_out, int out_size)
{
    (void)in_sizes; (void)n_in; (void)out_size;
    const float* x_in    = (const float*)d_in[0];
    const float* y_in    = (const float*)d_in[1];
    const float* t_in    = (const float*)d_in[2];
    const float* sstab   = (const float*)d_in[3];
    const float* w_qkv_s = (const float*)d_in[4];
    const float* b_qkv_s = (const float*)d_in[5];
    const float* w_proj_s = (const float*)d_in[6];
    const float* b_proj_s = (const float*)d_in[7];
    const float* w_qkv_t = (const float*)d_in[8];
    const float* b_qkv_t = (const float*)d_in[9];
    const float* w_proj_t = (const float*)d_in[10];
    const float* b_proj_t = (const float*)d_in[11];
    const float* wq_c  = (const float*)d_in[12];
    const float* bq_c  = (const float*)d_in[13];
    const float* wkv_c = (const float*)d_in[14];
    const float* bkv_c = (const float*)d_in[15];
    const float* wo_c  = (const float*)d_in[16];
    const float* bo_c  = (const float*)d_in[17];
    const float* w_fc1 = (const float*)d_in[18];
    const float* b_fc1 = (const float*)d_in[19];
    const float* w_fc2 = (const float*)d_in[20];
    const float* b_fc2 = (const float*)d_in[21];
    const float* f_cos = (const float*)d_in[22];
    const float* f_sin = (const float*)d_in[23];
    float* out = (float*)d_out;

    float* ss;   cudaGetSymbolAddress((void**)&ss, g_ss);
    __half *wt_qkv_s, *wt_proj_s, *wt_qkv_t, *wt_proj_t, *wt_q_c, *wt_kv_c, *wt_wo_c, *wt_fc1, *wt_fc2;
    __half *xm, *xh, *big, *attn, *kvc, *yh;
    cudaGetSymbolAddress((void**)&wt_qkv_s, g_wt_qkv_s);
    cudaGetSymbolAddress((void**)&wt_proj_s, g_wt_proj_s);
    cudaGetSymbolAddress((void**)&wt_qkv_t, g_wt_qkv_t);
    cudaGetSymbolAddress((void**)&wt_proj_t, g_wt_proj_t);
    cudaGetSymbolAddress((void**)&wt_q_c,  g_wt_q_c);
    cudaGetSymbolAddress((void**)&wt_kv_c, g_wt_kv_c);
    cudaGetSymbolAddress((void**)&wt_wo_c, g_wt_wo_c);
    cudaGetSymbolAddress((void**)&wt_fc1,  g_wt_fc1);
    cudaGetSymbolAddress((void**)&wt_fc2,  g_wt_fc2);
    cudaGetSymbolAddress((void**)&xm,   g_xm);
    cudaGetSymbolAddress((void**)&xh,   g_xh);
    cudaGetSymbolAddress((void**)&big,  g_big);
    cudaGetSymbolAddress((void**)&attn, g_attn);
    cudaGetSymbolAddress((void**)&kvc,  g_kvc);
    cudaGetSymbolAddress((void**)&yh,   g_yh);

    const int GEMM_SMEM = 98304;
    cudaFuncSetAttribute(hgemm_kernel<0>, cudaFuncAttributeMaxDynamicSharedMemorySize, GEMM_SMEM);
    cudaFuncSetAttribute(hgemm_kernel<1>, cudaFuncAttributeMaxDynamicSharedMemorySize, GEMM_SMEM);
    cudaFuncSetAttribute(hgemm_kernel<2>, cudaFuncAttributeMaxDynamicSharedMemorySize, GEMM_SMEM);
    cudaFuncSetAttribute(hgemm_kernel<3>, cudaFuncAttributeMaxDynamicSharedMemorySize, GEMM_SMEM);
    cudaFuncSetAttribute(hgemm_kernel<4>, cudaFuncAttributeMaxDynamicSharedMemorySize, GEMM_SMEM);
    cudaFuncSetAttribute(hgemm_dual_kernel, cudaFuncAttributeMaxDynamicSharedMemorySize, GEMM_SMEM);
    cudaFuncSetAttribute(mha_kernel, cudaFuncAttributeMaxDynamicSharedMemorySize, MHA_SMEM);
    cudaFuncSetAttribute(temporal_mma_kernel, cudaFuncAttributeMaxDynamicSharedMemorySize, TMP_SMEM);

    // ---- fused preprocessing ----
    TWPack pack;
    int tile_acc = 0;
    auto add = [&](int i, const float* w, __half* wt, int K, int N) {
        pack.e[i].w = w; pack.e[i].wt = wt; pack.e[i].K = K; pack.e[i].N = N;
        pack.e[i].tile0 = tile_acc;
        tile_acc += (K >> 5) * (N >> 5);
    };
    add(0, w_qkv_s,  wt_qkv_s,  1152, 3456);
    add(1, w_proj_s, wt_proj_s, 1152, 1152);
    add(2, w_qkv_t,  wt_qkv_t,  1152, 3456);
    add(3, w_proj_t, wt_proj_t, 1152, 1152);
    add(4, wq_c,     wt_q_c,    1152, 1152);
    add(5, wkv_c,    wt_kv_c,   1152, 2304);
    add(6, wo_c,     wt_wo_c,   1152, 1152);
    add(7, w_fc1,    wt_fc1,    1152, 4608);
    add(8, w_fc2,    wt_fc2,    4608, 1152);
    pack.n_tw  = tile_acc;
    pack.n_f2h = ((480 * 1152 / 4) + 255) / 256;
    pack.y = y_in; pack.yh = yh;
    pack.t = t_in; pack.table = sstab; pack.ss = ss;
    int n_ss_blocks = (B_SZ * SS_STRIDE + 255) / 256;
    preproc_kernel<<<tile_acc + pack.n_f2h + n_ss_blocks, 256>>>(pack);

    ln_mod_kernel<<<M_ROWS / 8, 256>>>(x_in, xm, ss, 0, 1);

    // spatial branch
    hgemm_kernel<0><<<dim3(27, 128), 256, GEMM_SMEM>>>(xm, wt_qkv_s, b_qkv_s,
        nullptr, big, M_ROWS, 3456, 1152, nullptr, nullptr, nullptr, nullptr);
    mha_kernel<<<dim3(2, 16, 64), 256, MHA_SMEM>>>(
        big, big + 1152, big + 2304, attn, 3456, 3456, 1152, 256, 256, 256);
    hgemm_kernel<1><<<dim3(9, 128), 256, GEMM_SMEM>>>(attn, wt_proj_s, b_proj_s,
        out, xh, M_ROWS, 1152, 1152, x_in, ss + 2 * C_DIM, nullptr, nullptr);

    // temporal branch
    hgemm_kernel<4><<<dim3(27, 128), 256, GEMM_SMEM>>>(xh, wt_qkv_t, b_qkv_t,
        nullptr, big, M_ROWS, 3456, 1152, nullptr, nullptr, f_cos, f_sin);
    temporal_mma_kernel<<<2048, 256, TMP_SMEM>>>(big, attn);
    hgemm_kernel<1><<<dim3(9, 128), 256, GEMM_SMEM>>>(attn, wt_proj_t, b_proj_t,
        out, xh, M_ROWS, 1152, 1152, out, ss + 2 * C_DIM, nullptr, nullptr);

    // cross attention: q_c GEMM + kvc GEMM fused into one launch
    hgemm_dual_kernel<<<dim3(18, 132), 256, GEMM_SMEM>>>(
        xh, wt_q_c, bq_c, xm,
        yh, wt_kv_c, bkv_c, kvc);
    mha_kernel<<<dim3(32, 16, 4), 256, MHA_SMEM>>>(
        xm, kvc, kvc + 1152, attn, 1152, 2304, 1152, 4096, 120, 120);
    hgemm_kernel<2><<<dim3(9, 128), 256, GEMM_SMEM>>>(attn, wt_wo_c, bo_c,
        out, nullptr, M_ROWS, 1152, 1152, out, nullptr, nullptr, nullptr);

    // MLP
    ln_mod_kernel<<<M_ROWS / 8, 256>>>(out, xm, ss, 3, 4);
    hgemm_kernel<3><<<dim3(36, 128), 256, GEMM_SMEM>>>(xm, wt_fc1, b_fc1,
        nullptr, big, M_ROWS, 4608, 1152, nullptr, nullptr, nullptr, nullptr);
    hgemm_kernel<1><<<dim3(9, 128), 256, GEMM_SMEM>>>(big, wt_fc2, b_fc2,
        out, nullptr, M_ROWS, 1152, 4608, out, ss + 5 * C_DIM, nullptr, nullptr);
}